// round 16
// baseline (speedup 1.0000x reference)
#include <cuda_runtime.h>
#include <cuda_fp16.h>
#include <math_constants.h>
#include <cstdint>

// Problem constants
#define NN 56
#define HW 3136          // 56*56
#define NV 29            // rfft columns: v in [0,28]
#define NF (NN*NV)       // 1624 retained frequencies
#define NB 32            // batch
#define CI 64
#define CO 128
#define OB 4096          // CO*NB
#define IB 2048          // CI*NB
#define OI 8192          // CO*CI
#define PADH 136         // padded K stride (halfs) for einsum mma tiles
#define PKA 122          // padded K stride for K=112 mma tiles
#define PKV 74           // padded K stride for ifft_v mma (58 used, 64 read)
#define PXF 72           // padded K stride for fwd stage-A (56 used, 64 read)

// ---------------- scratch (device globals; no runtime allocation allowed) ----
__device__ __align__(16) __half  g_KA[(size_t)NF * 16384];   // [f][o][k=2i+c] fp16  53MB
__device__ __align__(16) __half2 g_Xf[(size_t)NF * IB];      // [f][i*32+b] cplx     13MB
__device__ __align__(16) __half2 g_Yf[(size_t)NF * OB];      // [f][o*32+b] (x 1/HW) 27MB
__device__ __align__(16) __half2 g_Z [(size_t)NF * OB];      // [h*29+v][ob]         27MB
__device__ __align__(16) __half  g_Au[64 * PKA];             // ifft_u twiddle A
__device__ __align__(16) __half  g_Av[64 * PKV];             // ifft_v twiddle A
__device__ __align__(16) __half  g_Ff[64 * PKA];             // fwd stage-B twiddle A
__device__ __align__(16) __half  g_Bf[64 * PXF];             // fwd stage-A twiddle B

// ------- 0) constant twiddle matrices for all MMAs ---------------------------
// g_Au[h][2u]=cos(2pi h u/56), [2u+1]=sin  (inverse, e^{+i})
// g_Av[w][2v]: v=0->1; v=28->(-1)^w; else 2cos. [2v+1]: 0 or -2sin.
// g_Ff[u][2h]=cos(2pi u h/56), [2h+1]=-sin (forward, e^{-i})
// g_Bf[2v+d][w]: d=0 -> cos(2pi v w/56); d=1 -> -sin
__global__ void k_init_A() {
    int s = blockIdx.x * blockDim.x + threadIdx.x;
    const int N1 = 64 * PKA;
    const int N2 = N1 + 64 * PKV;
    const int N3 = N2 + 64 * PKA;
    const int N4 = N3 + 64 * PXF;
    if (s < N1) {
        int h = s / PKA, c = s - h * PKA;
        float val = 0.f;
        if (h < NN && c < 112) {
            int u = c >> 1;
            float ang = 2.0f * CUDART_PI_F * (float)((h * u) % NN) / (float)NN;
            val = (c & 1) ? sinf(ang) : cosf(ang);
        }
        g_Au[s] = __float2half(val);
    } else if (s < N2) {
        int s2 = s - N1;
        int w = s2 / PKV, c = s2 - w * PKV;
        float val = 0.f;
        if (w < NN && c < 58) {
            int v = c >> 1;
            if (v == 0)       val = (c & 1) ? 0.f : 1.f;
            else if (v == 28) val = (c & 1) ? 0.f : ((w & 1) ? -1.f : 1.f);
            else {
                float ang = 2.0f * CUDART_PI_F * (float)((v * w) % NN) / (float)NN;
                val = (c & 1) ? -2.0f * sinf(ang) : 2.0f * cosf(ang);
            }
        }
        g_Av[s2] = __float2half(val);
    } else if (s < N3) {
        int s2 = s - N2;
        int u = s2 / PKA, c = s2 - u * PKA;
        float val = 0.f;
        if (u < NN && c < 112) {
            int h = c >> 1;
            float ang = 2.0f * CUDART_PI_F * (float)((u * h) % NN) / (float)NN;
            val = (c & 1) ? -sinf(ang) : cosf(ang);
        }
        g_Ff[s2] = __float2half(val);
    } else if (s < N4) {
        int s2 = s - N3;
        int n = s2 / PXF, w = s2 - n * PXF;
        float val = 0.f;
        if (n < 58 && w < NN) {
            int v = n >> 1;
            float ang = 2.0f * CUDART_PI_F * (float)((v * w) % NN) / (float)NN;
            val = (n & 1) ? -sinf(ang) : cosf(ang);
        }
        g_Bf[s2] = __float2half(val);
    }
}

// ------- 1) build A tiles: g_KA[f][o][k], k=2i+c interleaved, fp16 -----------
__global__ void k_build_KA(const float* __restrict__ kr, const float* __restrict__ ki) {
    __shared__ float2 tile[32][33];     // [i_local][f_local]
    int fi0 = blockIdx.x * 32;
    int oi0 = blockIdx.y * 32;          // one o (oi0/64), i0 = oi0%64 (0 or 32)
    int tx = threadIdx.x, ty = threadIdx.y;
    int fi = fi0 + tx;
    bool valid = fi < NF;
    int u = fi / NV, v = fi - u * NV;
    int fsrc = u * NN + v;
#pragma unroll
    for (int k = 0; k < 4; k++) {
        int oi = oi0 + ty + k * 8;
        if (valid) {
            size_t src = (size_t)oi * HW + fsrc;
            tile[ty + k * 8][tx] = make_float2(kr[src], ki[src]);
        }
    }
    __syncthreads();

    int t = ty * 32 + tx;
    int f_local = t >> 3;
    int f = fi0 + f_local;
    if (f < NF) {
        int o  = oi0 >> 6;
        int i0 = oi0 & 63;
        __half2* dst = (__half2*)(g_KA + (size_t)f * 16384 + o * 128 + 2 * i0);
        int c0 = (t & 7) * 4;
#pragma unroll
        for (int r = 0; r < 4; r++) {
            int il = c0 + r;
            float2 kv = tile[il][f_local];
            dst[il] = __floats2half2_rn(kv.x, kv.y);
        }
    }
}

// ------- 2) forward rfft2 per (b,i) via two chained MMAs ---------------------
// stage A: A1[h][2v+d] = sum_w x[h,w] * g_Bf[2v+d][w]        (M=64,K=64,N=64)
// stage B: Xf[u][2v+d] = sum_k g_Ff[u][k] * B2[2v+d][k]      (M=64,K=112,N=64)
// B2 built from stage-A C-fragments: rows 2v=(r,-i), 2v+1=(i,r) over k=2h+c
__global__ void __launch_bounds__(256, 2) k_fwd_mma(const float* __restrict__ x) {
    extern __shared__ char smem[];
    __half* Xs = (__half*)smem;                 // [64][PXF]
    __half* Fb = Xs + 64 * PXF;                 // [64][PXF]
    __half* A2 = Fb + 64 * PXF;                 // [64][PKA]
    __half* B2 = A2 + 64 * PKA;                 // [64][PKA]
    int bi = blockIdx.x;
    int b = bi / CI, ci = bi % CI;
    int tid = threadIdx.x;
    int wid = tid >> 5, lane = tid & 31;
    int gid = lane >> 2, tig = lane & 3;
    int warpm = wid & 3, warpn = wid >> 2;

    // zero Xs; load constant tiles
    for (int t = tid; t < (64 * PXF) / 8; t += 256) ((uint4*)Xs)[t] = make_uint4(0, 0, 0, 0);
    for (int t = tid; t < (64 * PXF) / 8; t += 256) ((uint4*)Fb)[t] = ((const uint4*)g_Bf)[t];
    for (int t = tid; t < (64 * PKA) / 8; t += 256) ((uint4*)A2)[t] = ((const uint4*)g_Ff)[t];
    __syncthreads();

    // fill x plane (fp32 -> fp16), coalesced global reads
    const float* xp = x + (size_t)bi * HW;
    for (int t = tid; t < HW; t += 256) {
        int h = t / NN, w = t - h * NN;
        Xs[h * PXF + w] = __float2half(xp[t]);
    }
    __syncthreads();

    int m0 = warpm * 16, n0 = warpn * 32;

    // ---- stage A ----
    float acc[4][4];
#pragma unroll
    for (int j = 0; j < 4; j++)
#pragma unroll
        for (int q = 0; q < 4; q++) acc[j][q] = 0.f;
    {
        const __half* Ar0 = Xs + (m0 + gid) * PXF + 2 * tig;
        const __half* Ar1 = Ar0 + 8 * PXF;
        const __half* Br  = Fb + (n0 + gid) * PXF + 2 * tig;
#pragma unroll
        for (int kc = 0; kc < 4; kc++) {
            int k0 = kc * 16;
            uint32_t a0 = *(const uint32_t*)(Ar0 + k0);
            uint32_t a1 = *(const uint32_t*)(Ar1 + k0);
            uint32_t a2 = *(const uint32_t*)(Ar0 + k0 + 8);
            uint32_t a3 = *(const uint32_t*)(Ar1 + k0 + 8);
#pragma unroll
            for (int j = 0; j < 4; j++) {
                uint32_t b0 = *(const uint32_t*)(Br + j * 8 * PXF + k0);
                uint32_t b1 = *(const uint32_t*)(Br + j * 8 * PXF + k0 + 8);
                asm volatile(
                    "mma.sync.aligned.m16n8k16.row.col.f32.f16.f16.f32 "
                    "{%0,%1,%2,%3}, {%4,%5,%6,%7}, {%8,%9}, {%0,%1,%2,%3};"
                    : "+f"(acc[j][0]), "+f"(acc[j][1]), "+f"(acc[j][2]), "+f"(acc[j][3])
                    : "r"(a0), "r"(a1), "r"(a2), "r"(a3), "r"(b0), "r"(b1));
            }
        }
    }
    // epilogue A -> B2:  B2[2v][2h]=(r,-i)  B2[2v+1][2h]=(i,r)
    {
        int h0 = m0 + gid, h1 = h0 + 8;
#pragma unroll
        for (int j = 0; j < 4; j++) {
            int v2 = n0 + 8 * j + 2 * tig;        // = 2v (even)
            *(__half2*)(B2 + v2 * PKA + 2 * h0) =
                __floats2half2_rn(acc[j][0], -acc[j][1]);
            *(__half2*)(B2 + (v2 + 1) * PKA + 2 * h0) =
                __floats2half2_rn(acc[j][1], acc[j][0]);
            if (h1 < NN) {
                *(__half2*)(B2 + v2 * PKA + 2 * h1) =
                    __floats2half2_rn(acc[j][2], -acc[j][3]);
                *(__half2*)(B2 + (v2 + 1) * PKA + 2 * h1) =
                    __floats2half2_rn(acc[j][3], acc[j][2]);
            }
        }
    }
    __syncthreads();

    // ---- stage B ----
    float acc2[4][4];
#pragma unroll
    for (int j = 0; j < 4; j++)
#pragma unroll
        for (int q = 0; q < 4; q++) acc2[j][q] = 0.f;
    {
        const __half* Ar0 = A2 + (m0 + gid) * PKA + 2 * tig;
        const __half* Ar1 = Ar0 + 8 * PKA;
        const __half* Br  = B2 + (n0 + gid) * PKA + 2 * tig;
#pragma unroll
        for (int kc = 0; kc < 7; kc++) {
            int k0 = kc * 16;
            uint32_t a0 = *(const uint32_t*)(Ar0 + k0);
            uint32_t a1 = *(const uint32_t*)(Ar1 + k0);
            uint32_t a2 = *(const uint32_t*)(Ar0 + k0 + 8);
            uint32_t a3 = *(const uint32_t*)(Ar1 + k0 + 8);
#pragma unroll
            for (int j = 0; j < 4; j++) {
                uint32_t b0 = *(const uint32_t*)(Br + j * 8 * PKA + k0);
                uint32_t b1 = *(const uint32_t*)(Br + j * 8 * PKA + k0 + 8);
                asm volatile(
                    "mma.sync.aligned.m16n8k16.row.col.f32.f16.f16.f32 "
                    "{%0,%1,%2,%3}, {%4,%5,%6,%7}, {%8,%9}, {%0,%1,%2,%3};"
                    : "+f"(acc2[j][0]), "+f"(acc2[j][1]), "+f"(acc2[j][2]), "+f"(acc2[j][3])
                    : "r"(a0), "r"(a1), "r"(a2), "r"(a3), "r"(b0), "r"(b1));
            }
        }
    }
    // store Xf[(u*29+v)*IB + col]
    {
        int u0 = m0 + gid, u1 = u0 + 8;
        int col = ci * NB + b;
#pragma unroll
        for (int j = 0; j < 4; j++) {
            int v = (n0 >> 1) + 4 * j + tig;
            if (v < NV) {
                g_Xf[(size_t)(u0 * NV + v) * IB + col] =
                    __floats2half2_rn(acc2[j][0], acc2[j][1]);
                if (u1 < NN)
                    g_Xf[(size_t)(u1 * NV + v) * IB + col] =
                        __floats2half2_rn(acc2[j][2], acc2[j][3]);
            }
        }
    }
}

// ------- 3) mma.sync fp16 einsum, epilogue folds 1/HW, fp16 Yf out -----------
__global__ void __launch_bounds__(256, 3) k_einsum_mma() {
    extern __shared__ char smem[];
    __half* As = (__half*)smem;               // [128][PADH]
    __half* Bs = (__half*)smem + 128 * PADH;  // [64][PADH]
    int f = blockIdx.x;
    int tid = threadIdx.x;
    int wid = tid >> 5, lane = tid & 31;
    int gid = lane >> 2, tig = lane & 3;

    {
        const uint4* Ag = (const uint4*)(g_KA + (size_t)f * 16384);
#pragma unroll 4
        for (int t = tid; t < 2048; t += 256) {
            int row = t >> 4, ch = t & 15;
            *(uint4*)(As + row * PADH + ch * 8) = Ag[t];
        }
    }
    {
        const __half2* Xg = g_Xf + (size_t)f * IB;
#pragma unroll 4
        for (int t = tid; t < 2048; t += 256) {
            __half2 xv = Xg[t];
            int i = t >> 5, b = t & 31;
            __half xr = __low2half(xv), xi = __high2half(xv);
            __half2* r0 = (__half2*)(Bs + (2 * b) * PADH + 2 * i);
            r0[0]          = __halves2half2(xr, __hneg(xi));
            *(__half2*)((__half*)r0 + PADH) = __halves2half2(xi, xr);
        }
    }
    __syncthreads();

    int m0 = wid * 16;
    float acc[8][4];
#pragma unroll
    for (int j = 0; j < 8; j++)
#pragma unroll
        for (int q = 0; q < 4; q++) acc[j][q] = 0.f;

    const __half* Ar0 = As + (m0 + gid) * PADH + 2 * tig;
    const __half* Ar1 = Ar0 + 8 * PADH;
    const __half* Br  = Bs + gid * PADH + 2 * tig;

#pragma unroll
    for (int kc = 0; kc < 8; kc++) {
        int k0 = kc * 16;
        uint32_t a0 = *(const uint32_t*)(Ar0 + k0);
        uint32_t a1 = *(const uint32_t*)(Ar1 + k0);
        uint32_t a2 = *(const uint32_t*)(Ar0 + k0 + 8);
        uint32_t a3 = *(const uint32_t*)(Ar1 + k0 + 8);
#pragma unroll
        for (int j = 0; j < 8; j++) {
            uint32_t b0 = *(const uint32_t*)(Br + j * 8 * PADH + k0);
            uint32_t b1 = *(const uint32_t*)(Br + j * 8 * PADH + k0 + 8);
            asm volatile(
                "mma.sync.aligned.m16n8k16.row.col.f32.f16.f16.f32 "
                "{%0,%1,%2,%3}, {%4,%5,%6,%7}, {%8,%9}, {%0,%1,%2,%3};"
                : "+f"(acc[j][0]), "+f"(acc[j][1]), "+f"(acc[j][2]), "+f"(acc[j][3])
                : "r"(a0), "r"(a1), "r"(a2), "r"(a3), "r"(b0), "r"(b1));
        }
    }

    const float sInv = 1.0f / (float)HW;
    __half2* Yf = g_Yf + (size_t)f * OB;
#pragma unroll
    for (int j = 0; j < 8; j++) {
        int b = 4 * j + tig;
        Yf[(m0 + gid) * NB + b]     = __floats2half2_rn(acc[j][0] * sInv, acc[j][1] * sInv);
        Yf[(m0 + gid + 8) * NB + b] = __floats2half2_rn(acc[j][2] * sInv, acc[j][3] * sInv);
    }
}

// ------- 4) mma inverse over u: Z[h,ob] = sum_u conjF[h,u] Y[u,ob], per v ----
__global__ void __launch_bounds__(256, 3) k_ifft_u_mma() {
    extern __shared__ char smem[];
    __half* As = (__half*)smem;               // [64][PKA]
    __half* Bs = As + 64 * PKA;               // [128][PKA]
    int v = blockIdx.y, obt = blockIdx.x;
    int tid = threadIdx.x;
    int wid = tid >> 5, lane = tid & 31;
    int gid = lane >> 2, tig = lane & 3;
    int warpm = wid & 3, warpn = wid >> 2;

    {
        const uint4* Ag = (const uint4*)g_Au;
        uint4* Ad = (uint4*)As;
#pragma unroll 4
        for (int t = tid; t < (64 * PKA) / 8; t += 256) Ad[t] = Ag[t];
    }
    for (int t = tid; t < NN * 64; t += 256) {
        int u = t >> 6, obl = t & 63;
        __half2 y = g_Yf[(size_t)(u * NV + v) * OB + obt * 64 + obl];
        __half yr = __low2half(y), yi = __high2half(y);
        *(__half2*)(Bs + (2 * obl) * PKA + 2 * u)     = __halves2half2(yr, __hneg(yi));
        *(__half2*)(Bs + (2 * obl + 1) * PKA + 2 * u) = __halves2half2(yi, yr);
    }
    __syncthreads();

    int m0 = warpm * 16, n0 = warpn * 64;
    float acc[8][4];
#pragma unroll
    for (int j = 0; j < 8; j++)
#pragma unroll
        for (int q = 0; q < 4; q++) acc[j][q] = 0.f;

    const __half* Ar0 = As + (m0 + gid) * PKA + 2 * tig;
    const __half* Ar1 = Ar0 + 8 * PKA;
    const __half* Br  = Bs + (n0 + gid) * PKA + 2 * tig;

#pragma unroll
    for (int kc = 0; kc < 7; kc++) {
        int k0 = kc * 16;
        uint32_t a0 = *(const uint32_t*)(Ar0 + k0);
        uint32_t a1 = *(const uint32_t*)(Ar1 + k0);
        uint32_t a2 = *(const uint32_t*)(Ar0 + k0 + 8);
        uint32_t a3 = *(const uint32_t*)(Ar1 + k0 + 8);
#pragma unroll
        for (int j = 0; j < 8; j++) {
            uint32_t b0 = *(const uint32_t*)(Br + j * 8 * PKA + k0);
            uint32_t b1 = *(const uint32_t*)(Br + j * 8 * PKA + k0 + 8);
            asm volatile(
                "mma.sync.aligned.m16n8k16.row.col.f32.f16.f16.f32 "
                "{%0,%1,%2,%3}, {%4,%5,%6,%7}, {%8,%9}, {%0,%1,%2,%3};"
                : "+f"(acc[j][0]), "+f"(acc[j][1]), "+f"(acc[j][2]), "+f"(acc[j][3])
                : "r"(a0), "r"(a1), "r"(a2), "r"(a3), "r"(b0), "r"(b1));
        }
    }

    int h0 = m0 + gid, h1 = h0 + 8;
#pragma unroll
    for (int j = 0; j < 8; j++) {
        int q = warpn * 32 + 4 * j + tig;
        g_Z[(size_t)(h0 * NV + v) * OB + obt * 64 + q] =
            __floats2half2_rn(acc[j][0], acc[j][1]);
        if (h1 < NN)
            g_Z[(size_t)(h1 * NV + v) * OB + obt * 64 + q] =
                __floats2half2_rn(acc[j][2], acc[j][3]);
    }
}

// ------- 5) mma Hermitian inverse over v + bias + final layout, per h --------
__global__ void __launch_bounds__(256, 4) k_ifft_v_mma(const float* __restrict__ bias,
                                                       float* __restrict__ out) {
    extern __shared__ char smem[];
    __half* As = (__half*)smem;               // [64][PKV]
    __half* Bs = As + 64 * PKV;               // [64][PKV]
    int h = blockIdx.y, obt = blockIdx.x;
    int tid = threadIdx.x;
    int wid = tid >> 5, lane = tid & 31;
    int gid = lane >> 2, tig = lane & 3;
    int warpm = wid & 3, warpn = wid >> 2;

    {
        const uint4* Ag = (const uint4*)g_Av;
#pragma unroll 2
        for (int t = tid; t < (64 * PKV) / 8; t += 256) ((uint4*)As)[t] = Ag[t];
    }
    for (int t = tid; t < 64 * 3; t += 256) {
        int c = t >> 6, obl = t & 63;
        *(__half2*)(Bs + obl * PKV + 58 + 2 * c) = __float2half2_rn(0.f);
    }
    for (int t = tid; t < NV * 64; t += 256) {
        int vv = t >> 6, obl = t & 63;
        *(__half2*)(Bs + obl * PKV + 2 * vv) =
            g_Z[(size_t)(h * NV + vv) * OB + obt * 64 + obl];
    }
    __syncthreads();

    int m0 = warpm * 16, n0 = warpn * 32;
    float acc[4][4];
#pragma unroll
    for (int j = 0; j < 4; j++)
#pragma unroll
        for (int q = 0; q < 4; q++) acc[j][q] = 0.f;

    const __half* Ar0 = As + (m0 + gid) * PKV + 2 * tig;
    const __half* Ar1 = Ar0 + 8 * PKV;
    const __half* Br  = Bs + (n0 + gid) * PKV + 2 * tig;

#pragma unroll
    for (int kc = 0; kc < 4; kc++) {
        int k0 = kc * 16;
        uint32_t a0 = *(const uint32_t*)(Ar0 + k0);
        uint32_t a1 = *(const uint32_t*)(Ar1 + k0);
        uint32_t a2 = *(const uint32_t*)(Ar0 + k0 + 8);
        uint32_t a3 = *(const uint32_t*)(Ar1 + k0 + 8);
#pragma unroll
        for (int j = 0; j < 4; j++) {
            uint32_t b0 = *(const uint32_t*)(Br + j * 8 * PKV + k0);
            uint32_t b1 = *(const uint32_t*)(Br + j * 8 * PKV + k0 + 8);
            asm volatile(
                "mma.sync.aligned.m16n8k16.row.col.f32.f16.f16.f32 "
                "{%0,%1,%2,%3}, {%4,%5,%6,%7}, {%8,%9}, {%0,%1,%2,%3};"
                : "+f"(acc[j][0]), "+f"(acc[j][1]), "+f"(acc[j][2]), "+f"(acc[j][3])
                : "r"(a0), "r"(a1), "r"(a2), "r"(a3), "r"(b0), "r"(b1));
        }
    }

    int w0 = m0 + gid, w1 = w0 + 8;
#pragma unroll
    for (int j = 0; j < 4; j++) {
        int col = n0 + 8 * j + 2 * tig;       // even
        int ob = obt * 64 + col;
        int o = ob >> 5, bb = ob & 31;        // ob = o*32+b, b even
        float bv = bias[o];
        size_t base0 = (size_t)(bb * CO + o) * HW + h * NN;
        size_t base1 = (size_t)((bb + 1) * CO + o) * HW + h * NN;
        out[base0 + w0] = acc[j][0] + bv;
        out[base1 + w0] = acc[j][1] + bv;
        if (w1 < NN) {
            out[base0 + w1] = acc[j][2] + bv;
            out[base1 + w1] = acc[j][3] + bv;
        }
    }
}

// ---------------- launch -----------------------------------------------------
extern "C" void kernel_launch(void* const* d_in, const int* in_sizes, int n_in,
                              void* d_out, int out_size) {
    const float* x    = (const float*)d_in[0];   // [32,64,56,56]
    const float* kr   = (const float*)d_in[1];   // [128,64,56,56]
    const float* ki   = (const float*)d_in[2];   // [128,64,56,56]
    const float* bias = (const float*)d_in[3];   // [128]
    float* out = (float*)d_out;                  // [32,128,56,56]

    const int smem_fwd = 64 * (2 * PXF + 2 * PKA) * (int)sizeof(__half);  // 49664
    const int smem_mma = (128 + 64) * PADH * (int)sizeof(__half);         // 52224
    const int smem_iu  = (64 + 128) * PKA * (int)sizeof(__half);          // 46848
    const int smem_iv  = (64 + 64) * PKV * (int)sizeof(__half);           // 18944
    cudaFuncSetAttribute(k_fwd_mma, cudaFuncAttributeMaxDynamicSharedMemorySize, smem_fwd);
    cudaFuncSetAttribute(k_einsum_mma, cudaFuncAttributeMaxDynamicSharedMemorySize, smem_mma);
    cudaFuncSetAttribute(k_ifft_u_mma, cudaFuncAttributeMaxDynamicSharedMemorySize, smem_iu);
    cudaFuncSetAttribute(k_ifft_v_mma, cudaFuncAttributeMaxDynamicSharedMemorySize, smem_iv);

    const int n_init = 64 * (PKA + PKV + PKA + PXF);
    k_init_A<<<(n_init + 255) / 256, 256>>>();
    k_build_KA<<<dim3((NF + 31) / 32, OI / 32), dim3(32, 8)>>>(kr, ki);
    k_fwd_mma<<<IB, 256, smem_fwd>>>(x);
    k_einsum_mma<<<NF, 256, smem_mma>>>();
    k_ifft_u_mma<<<dim3(64, NV), 256, smem_iu>>>();
    k_ifft_v_mma<<<dim3(64, NN), 256, smem_iv>>>(bias, out);
}

// round 17
// speedup vs baseline: 1.2290x; 1.2290x over previous
#include <cuda_runtime.h>
#include <cuda_fp16.h>
#include <math_constants.h>
#include <cstdint>

// Problem constants
#define NN 56
#define HW 3136          // 56*56
#define NV 29            // rfft columns: v in [0,28]
#define NF (NN*NV)       // 1624 retained frequencies
#define NB 32            // batch
#define CI 64
#define CO 128
#define OB 4096          // CO*NB
#define IB 2048          // CI*NB
#define OI 8192          // CO*CI
#define PADH 136         // padded K stride (halfs) for einsum B tile
#define PKA 122          // padded K stride for ifft_u mma (112 used)
#define PKV 74           // padded K stride for ifft_v mma (58 used, 64 read)

// ---------------- scratch (device globals; no runtime allocation allowed) ----
__device__ __align__(16) float2  g_F [HW];                   // twiddles
__device__ __align__(16) __half  g_KA[(size_t)NF * 16384];   // [f][o][k=2i+c] fp16  53MB
__device__ __align__(16) __half2 g_Xf[(size_t)NF * IB];      // [f][i*32+b] cplx     13MB
__device__ __align__(16) __half2 g_Yf[(size_t)NF * OB];      // [f][o*32+b] (x 1/HW) 27MB
__device__ __align__(16) __half2 g_Z [(size_t)NF * OB];      // [h*29+v][ob]         27MB
__device__ __align__(16) __half  g_Au[64 * PKA];             // ifft_u twiddle A
__device__ __align__(16) __half  g_Av[64 * PKV];             // ifft_v twiddle A

// ---------------- 0) twiddle init -------------------------------------------
__global__ void k_init_F() {
    int idx = blockIdx.x * blockDim.x + threadIdx.x;
    if (idx < HW) {
        int j = idx / NN, k = idx % NN;
        int m = (j * k) % NN;
        float ang = -2.0f * CUDART_PI_F * (float)m / (float)NN;
        float s, c;
        sincosf(ang, &s, &c);
        g_F[idx] = make_float2(c, s);
    }
}

// ------- 0b) constant A matrices for the two inverse-transform MMAs ----------
__global__ void k_init_A() {
    int s = blockIdx.x * blockDim.x + threadIdx.x;
    if (s < 64 * PKA) {
        int h = s / PKA, c = s - h * PKA;
        float val = 0.f;
        if (h < NN && c < 112) {
            int u = c >> 1;
            float ang = 2.0f * CUDART_PI_F * (float)((h * u) % NN) / (float)NN;
            val = (c & 1) ? sinf(ang) : cosf(ang);
        }
        g_Au[s] = __float2half(val);
    } else if (s < 64 * PKA + 64 * PKV) {
        int s2 = s - 64 * PKA;
        int w = s2 / PKV, c = s2 - w * PKV;
        float val = 0.f;
        if (w < NN && c < 58) {
            int v = c >> 1;
            if (v == 0)       val = (c & 1) ? 0.f : 1.f;
            else if (v == 28) val = (c & 1) ? 0.f : ((w & 1) ? -1.f : 1.f);
            else {
                float ang = 2.0f * CUDART_PI_F * (float)((v * w) % NN) / (float)NN;
                val = (c & 1) ? -2.0f * sinf(ang) : 2.0f * cosf(ang);
            }
        }
        g_Av[s2] = __float2half(val);
    }
}

// ------- 1) build A tiles: g_KA[f][o][k], k=2i+c interleaved, fp16 -----------
__global__ void k_build_KA(const float* __restrict__ kr, const float* __restrict__ ki) {
    __shared__ float2 tile[32][33];     // [i_local][f_local]
    int fi0 = blockIdx.x * 32;
    int oi0 = blockIdx.y * 32;          // one o (oi0/64), i0 = oi0%64 (0 or 32)
    int tx = threadIdx.x, ty = threadIdx.y;
    int fi = fi0 + tx;
    bool valid = fi < NF;
    int u = fi / NV, v = fi - u * NV;
    int fsrc = u * NN + v;
#pragma unroll
    for (int k = 0; k < 4; k++) {
        int oi = oi0 + ty + k * 8;
        if (valid) {
            size_t src = (size_t)oi * HW + fsrc;
            tile[ty + k * 8][tx] = make_float2(kr[src], ki[src]);
        }
    }
    __syncthreads();

    int t = ty * 32 + tx;
    int f_local = t >> 3;
    int f = fi0 + f_local;
    if (f < NF) {
        int o  = oi0 >> 6;
        int i0 = oi0 & 63;
        __half2* dst = (__half2*)(g_KA + (size_t)f * 16384 + o * 128 + 2 * i0);
        int c0 = (t & 7) * 4;
#pragma unroll
        for (int r = 0; r < 4; r++) {
            int il = c0 + r;
            float2 kv = tile[il][f_local];
            dst[il] = __floats2half2_rn(kv.x, kv.y);
        }
    }
}

// ------- 2) forward rfft2 per (b,i), conjugate-pair factorized ---------------
__global__ void k_fwd_fft(const float* __restrict__ x) {
    extern __shared__ char smem[];
    float*  xs  = (float*)smem;                            // [3136]
    float2* Fs  = (float2*)(smem + HW * sizeof(float));    // [29][56]
    float2* A1  = Fs + 29 * NN;                            // [56][30]
    float2* sdm = A1 + NN * 30;                            // [56][28]

    int bi = blockIdx.x;
    int b  = bi / CI, ci = bi % CI;
    int tid = threadIdx.x;

    for (int t = tid; t < 29 * NN; t += 256) Fs[t] = g_F[t];
    for (int t = tid; t < HW; t += 256) xs[t] = x[(size_t)bi * HW + t];
    __syncthreads();

    for (int t = tid; t < NN * 28; t += 256) {
        int h = t / 28, w = t - h * 28;
        const float* xr = xs + h * NN;
        sdm[t] = (w == 0) ? make_float2(xr[0], xr[28])
                          : make_float2(xr[w] + xr[NN - w], xr[w] - xr[NN - w]);
    }
    __syncthreads();

    int lane = tid & 31;
    int grp  = tid >> 5;

    {   // stage a
        float ar[7], ai[7];
        float sgn = (lane & 1) ? -1.f : 1.f;
#pragma unroll
        for (int j = 0; j < 7; j++) {
            float2 sd0 = sdm[(grp * 7 + j) * 28];
            ar[j] = sd0.x + sgn * sd0.y;
            ai[j] = 0.f;
        }
        for (int w = 1; w < 28; w++) {
            float2 fv = Fs[w * NN + lane];
#pragma unroll
            for (int j = 0; j < 7; j++) {
                float2 sd = sdm[(grp * 7 + j) * 28 + w];
                ar[j] += fv.x * sd.x;
                ai[j] += fv.y * sd.y;
            }
        }
        if (lane < NV) {
#pragma unroll
            for (int j = 0; j < 7; j++)
                A1[(grp * 7 + j) * 30 + lane] = make_float2(ar[j], ai[j]);
        }
    }
    __syncthreads();

    {   // stage b: u-pairs via separated sums
        float Sap[4], Sbq[4], Saq[4], Sbp[4];
#pragma unroll
        for (int j = 0; j < 4; j++) { Sap[j] = Sbq[j] = Saq[j] = Sbp[j] = 0.f; }
        for (int h = 0; h < NN; h++) {
            float2 av = A1[h * 30 + lane];
#pragma unroll
            for (int j = 0; j < 4; j++) {
                int p = grp + 8 * j;
                float2 fv = Fs[(p & 31) * NN + h];   // p>28 discarded; in-bounds of smem
                Sap[j] += fv.x * av.x;
                Sbq[j] += fv.y * av.y;
                Saq[j] += fv.x * av.y;
                Sbp[j] += fv.y * av.x;
            }
        }
        if (lane < NV) {
            int col = ci * NB + b;
#pragma unroll
            for (int j = 0; j < 4; j++) {
                int p = grp + 8 * j;
                if (p <= 28) {
                    g_Xf[(size_t)(p * NV + lane) * IB + col] =
                        __floats2half2_rn(Sap[j] - Sbq[j], Saq[j] + Sbp[j]);
                    if (p != 0 && p != 28)
                        g_Xf[(size_t)((NN - p) * NV + lane) * IB + col] =
                            __floats2half2_rn(Sap[j] + Sbq[j], Saq[j] - Sbp[j]);
                }
            }
        }
    }
}

// ------- 3) mma.sync fp16 einsum: A fragments direct from global, B in SMEM --
__global__ void __launch_bounds__(256, 4) k_einsum_mma() {
    extern __shared__ char smem[];
    __half* Bs = (__half*)smem;               // [64][PADH] only
    int f = blockIdx.x;
    int tid = threadIdx.x;
    int wid = tid >> 5, lane = tid & 31;
    int gid = lane >> 2, tig = lane & 3;

    // build B tile: row 2b = (Xr, -Xi) interleaved over k=2i+c; row 2b+1 = (Xi, Xr)
    {
        const __half2* Xg = g_Xf + (size_t)f * IB;
#pragma unroll 4
        for (int t = tid; t < 2048; t += 256) {
            __half2 xv = Xg[t];
            int i = t >> 5, b = t & 31;
            __half xr = __low2half(xv), xi = __high2half(xv);
            __half2* r0 = (__half2*)(Bs + (2 * b) * PADH + 2 * i);
            r0[0]          = __halves2half2(xr, __hneg(xi));
            *(__half2*)((__half*)r0 + PADH) = __halves2half2(xi, xr);
        }
    }
    __syncthreads();

    int m0 = wid * 16;
    float acc[8][4];
#pragma unroll
    for (int j = 0; j < 8; j++)
#pragma unroll
        for (int q = 0; q < 4; q++) acc[j][q] = 0.f;

    // A fragments straight from global: row stride 128 halfs, each row one warp's
    const __half* Ag  = g_KA + (size_t)f * 16384;
    const __half* Ar0 = Ag + (m0 + gid) * 128 + 2 * tig;
    const __half* Ar1 = Ar0 + 8 * 128;
    const __half* Br  = Bs + gid * PADH + 2 * tig;

#pragma unroll
    for (int kc = 0; kc < 8; kc++) {
        int k0 = kc * 16;
        uint32_t a0 = *(const uint32_t*)(Ar0 + k0);
        uint32_t a1 = *(const uint32_t*)(Ar1 + k0);
        uint32_t a2 = *(const uint32_t*)(Ar0 + k0 + 8);
        uint32_t a3 = *(const uint32_t*)(Ar1 + k0 + 8);
#pragma unroll
        for (int j = 0; j < 8; j++) {
            uint32_t b0 = *(const uint32_t*)(Br + j * 8 * PADH + k0);
            uint32_t b1 = *(const uint32_t*)(Br + j * 8 * PADH + k0 + 8);
            asm volatile(
                "mma.sync.aligned.m16n8k16.row.col.f32.f16.f16.f32 "
                "{%0,%1,%2,%3}, {%4,%5,%6,%7}, {%8,%9}, {%0,%1,%2,%3};"
                : "+f"(acc[j][0]), "+f"(acc[j][1]), "+f"(acc[j][2]), "+f"(acc[j][3])
                : "r"(a0), "r"(a1), "r"(a2), "r"(a3), "r"(b0), "r"(b1));
        }
    }

    const float sInv = 1.0f / (float)HW;
    __half2* Yf = g_Yf + (size_t)f * OB;
#pragma unroll
    for (int j = 0; j < 8; j++) {
        int b = 4 * j + tig;
        Yf[(m0 + gid) * NB + b]     = __floats2half2_rn(acc[j][0] * sInv, acc[j][1] * sInv);
        Yf[(m0 + gid + 8) * NB + b] = __floats2half2_rn(acc[j][2] * sInv, acc[j][3] * sInv);
    }
}

// ------- 4) mma inverse over u: Z[h,ob] = sum_u conjF[h,u] Y[u,ob], per v ----
__global__ void __launch_bounds__(256, 3) k_ifft_u_mma() {
    extern __shared__ char smem[];
    __half* As = (__half*)smem;               // [64][PKA]
    __half* Bs = As + 64 * PKA;               // [128][PKA]
    int v = blockIdx.y, obt = blockIdx.x;
    int tid = threadIdx.x;
    int wid = tid >> 5, lane = tid & 31;
    int gid = lane >> 2, tig = lane & 3;
    int warpm = wid & 3, warpn = wid >> 2;

    {
        const uint4* Ag = (const uint4*)g_Au;
        uint4* Ad = (uint4*)As;
#pragma unroll 4
        for (int t = tid; t < (64 * PKA) / 8; t += 256) Ad[t] = Ag[t];
    }
    for (int t = tid; t < NN * 64; t += 256) {
        int u = t >> 6, obl = t & 63;
        __half2 y = g_Yf[(size_t)(u * NV + v) * OB + obt * 64 + obl];
        __half yr = __low2half(y), yi = __high2half(y);
        *(__half2*)(Bs + (2 * obl) * PKA + 2 * u)     = __halves2half2(yr, __hneg(yi));
        *(__half2*)(Bs + (2 * obl + 1) * PKA + 2 * u) = __halves2half2(yi, yr);
    }
    __syncthreads();

    int m0 = warpm * 16, n0 = warpn * 64;
    float acc[8][4];
#pragma unroll
    for (int j = 0; j < 8; j++)
#pragma unroll
        for (int q = 0; q < 4; q++) acc[j][q] = 0.f;

    const __half* Ar0 = As + (m0 + gid) * PKA + 2 * tig;
    const __half* Ar1 = Ar0 + 8 * PKA;
    const __half* Br  = Bs + (n0 + gid) * PKA + 2 * tig;

#pragma unroll
    for (int kc = 0; kc < 7; kc++) {
        int k0 = kc * 16;
        uint32_t a0 = *(const uint32_t*)(Ar0 + k0);
        uint32_t a1 = *(const uint32_t*)(Ar1 + k0);
        uint32_t a2 = *(const uint32_t*)(Ar0 + k0 + 8);
        uint32_t a3 = *(const uint32_t*)(Ar1 + k0 + 8);
#pragma unroll
        for (int j = 0; j < 8; j++) {
            uint32_t b0 = *(const uint32_t*)(Br + j * 8 * PKA + k0);
            uint32_t b1 = *(const uint32_t*)(Br + j * 8 * PKA + k0 + 8);
            asm volatile(
                "mma.sync.aligned.m16n8k16.row.col.f32.f16.f16.f32 "
                "{%0,%1,%2,%3}, {%4,%5,%6,%7}, {%8,%9}, {%0,%1,%2,%3};"
                : "+f"(acc[j][0]), "+f"(acc[j][1]), "+f"(acc[j][2]), "+f"(acc[j][3])
                : "r"(a0), "r"(a1), "r"(a2), "r"(a3), "r"(b0), "r"(b1));
        }
    }

    int h0 = m0 + gid, h1 = h0 + 8;
#pragma unroll
    for (int j = 0; j < 8; j++) {
        int q = warpn * 32 + 4 * j + tig;
        g_Z[(size_t)(h0 * NV + v) * OB + obt * 64 + q] =
            __floats2half2_rn(acc[j][0], acc[j][1]);
        if (h1 < NN)
            g_Z[(size_t)(h1 * NV + v) * OB + obt * 64 + q] =
                __floats2half2_rn(acc[j][2], acc[j][3]);
    }
}

// ------- 5) mma Hermitian inverse over v + bias + final layout, per h --------
__global__ void __launch_bounds__(256, 4) k_ifft_v_mma(const float* __restrict__ bias,
                                                       float* __restrict__ out) {
    extern __shared__ char smem[];
    __half* As = (__half*)smem;               // [64][PKV]
    __half* Bs = As + 64 * PKV;               // [64][PKV]
    int h = blockIdx.y, obt = blockIdx.x;
    int tid = threadIdx.x;
    int wid = tid >> 5, lane = tid & 31;
    int gid = lane >> 2, tig = lane & 3;
    int warpm = wid & 3, warpn = wid >> 2;

    {
        const uint4* Ag = (const uint4*)g_Av;
#pragma unroll 2
        for (int t = tid; t < (64 * PKV) / 8; t += 256) ((uint4*)As)[t] = Ag[t];
    }
    for (int t = tid; t < 64 * 3; t += 256) {
        int c = t >> 6, obl = t & 63;
        *(__half2*)(Bs + obl * PKV + 58 + 2 * c) = __float2half2_rn(0.f);
    }
    for (int t = tid; t < NV * 64; t += 256) {
        int vv = t >> 6, obl = t & 63;
        *(__half2*)(Bs + obl * PKV + 2 * vv) =
            g_Z[(size_t)(h * NV + vv) * OB + obt * 64 + obl];
    }
    __syncthreads();

    int m0 = warpm * 16, n0 = warpn * 32;
    float acc[4][4];
#pragma unroll
    for (int j = 0; j < 4; j++)
#pragma unroll
        for (int q = 0; q < 4; q++) acc[j][q] = 0.f;

    const __half* Ar0 = As + (m0 + gid) * PKV + 2 * tig;
    const __half* Ar1 = Ar0 + 8 * PKV;
    const __half* Br  = Bs + (n0 + gid) * PKV + 2 * tig;

#pragma unroll
    for (int kc = 0; kc < 4; kc++) {
        int k0 = kc * 16;
        uint32_t a0 = *(const uint32_t*)(Ar0 + k0);
        uint32_t a1 = *(const uint32_t*)(Ar1 + k0);
        uint32_t a2 = *(const uint32_t*)(Ar0 + k0 + 8);
        uint32_t a3 = *(const uint32_t*)(Ar1 + k0 + 8);
#pragma unroll
        for (int j = 0; j < 4; j++) {
            uint32_t b0 = *(const uint32_t*)(Br + j * 8 * PKV + k0);
            uint32_t b1 = *(const uint32_t*)(Br + j * 8 * PKV + k0 + 8);
            asm volatile(
                "mma.sync.aligned.m16n8k16.row.col.f32.f16.f16.f32 "
                "{%0,%1,%2,%3}, {%4,%5,%6,%7}, {%8,%9}, {%0,%1,%2,%3};"
                : "+f"(acc[j][0]), "+f"(acc[j][1]), "+f"(acc[j][2]), "+f"(acc[j][3])
                : "r"(a0), "r"(a1), "r"(a2), "r"(a3), "r"(b0), "r"(b1));
        }
    }

    int w0 = m0 + gid, w1 = w0 + 8;
#pragma unroll
    for (int j = 0; j < 4; j++) {
        int col = n0 + 8 * j + 2 * tig;       // even
        int ob = obt * 64 + col;
        int o = ob >> 5, bb = ob & 31;        // ob = o*32+b, b even
        float bv = bias[o];
        size_t base0 = (size_t)(bb * CO + o) * HW + h * NN;
        size_t base1 = (size_t)((bb + 1) * CO + o) * HW + h * NN;
        out[base0 + w0] = acc[j][0] + bv;
        out[base1 + w0] = acc[j][1] + bv;
        if (w1 < NN) {
            out[base0 + w1] = acc[j][2] + bv;
            out[base1 + w1] = acc[j][3] + bv;
        }
    }
}

// ---------------- launch -----------------------------------------------------
extern "C" void kernel_launch(void* const* d_in, const int* in_sizes, int n_in,
                              void* d_out, int out_size) {
    const float* x    = (const float*)d_in[0];   // [32,64,56,56]
    const float* kr   = (const float*)d_in[1];   // [128,64,56,56]
    const float* ki   = (const float*)d_in[2];   // [128,64,56,56]
    const float* bias = (const float*)d_in[3];   // [128]
    float* out = (float*)d_out;                  // [32,128,56,56]

    const int smem_fwd = HW * (int)sizeof(float)
                       + (29 * NN + NN * 30 + NN * 28) * (int)sizeof(float2);
    const int smem_mma = 64 * PADH * (int)sizeof(__half);            // 17408
    const int smem_iu  = (64 + 128) * PKA * (int)sizeof(__half);     // 46848
    const int smem_iv  = (64 + 64) * PKV * (int)sizeof(__half);      // 18944
    cudaFuncSetAttribute(k_fwd_fft, cudaFuncAttributeMaxDynamicSharedMemorySize, smem_fwd);
    cudaFuncSetAttribute(k_einsum_mma, cudaFuncAttributeMaxDynamicSharedMemorySize, smem_mma);
    cudaFuncSetAttribute(k_ifft_u_mma, cudaFuncAttributeMaxDynamicSharedMemorySize, smem_iu);
    cudaFuncSetAttribute(k_ifft_v_mma, cudaFuncAttributeMaxDynamicSharedMemorySize, smem_iv);

    k_init_F<<<(HW + 255) / 256, 256>>>();
    k_init_A<<<(64 * PKA + 64 * PKV + 255) / 256, 256>>>();
    k_build_KA<<<dim3((NF + 31) / 32, OI / 32), dim3(32, 8)>>>(kr, ki);
    k_fwd_fft<<<IB, 256, smem_fwd>>>(x);
    k_einsum_mma<<<NF, 256, smem_mma>>>();
    k_ifft_u_mma<<<dim3(64, NV), 256, smem_iu>>>();
    k_ifft_v_mma<<<dim3(64, NN), 256, smem_iv>>>(bias, out);
}